// round 13
// baseline (speedup 1.0000x reference)
#include <cuda_runtime.h>
#include <cuda_bf16.h>
#include <cstdint>

#define T_STEPS 1024
#define BATCH   512
#define DIM     128
#define GATES   384

// ---------------- device scratch ----------------
__device__ float g_bc[GATES];
__device__ __nv_bfloat16 g_Bh[3 * 16384];                // Wc hi: [nt][row][k]
__device__ __nv_bfloat16 g_Bl[3 * 16384];                // Wc lo
__device__ float g_GI[(size_t)T_STEPS * BATCH * GATES];  // 805 MB scratch

// ---------------- helpers ----------------
__device__ __forceinline__ float tanhf_fast(float x) {
    float y; asm("tanh.approx.f32 %0, %1;" : "=f"(y) : "f"(x)); return y;
}
__device__ __forceinline__ float sigm_fast(float x) {
    return fmaf(0.5f, tanhf_fast(0.5f * x), 0.5f);
}
__device__ __forceinline__ uint32_t smem_u32(const void* p) {
    uint32_t a;
    asm("{ .reg .u64 t; cvta.to.shared.u64 t, %1; cvt.u32.u64 %0, t; }" : "=r"(a) : "l"(p));
    return a;
}
__device__ __forceinline__ void ldsm4(uint32_t& r0, uint32_t& r1, uint32_t& r2, uint32_t& r3,
                                      uint32_t addr) {
    asm volatile("ldmatrix.sync.aligned.m8n8.x4.shared.b16 {%0,%1,%2,%3}, [%4];"
                 : "=r"(r0), "=r"(r1), "=r"(r2), "=r"(r3) : "r"(addr));
}
__device__ __forceinline__ void ldsm2t(uint32_t& r0, uint32_t& r1, uint32_t addr) {
    asm volatile("ldmatrix.sync.aligned.m8n8.x2.trans.shared.b16 {%0,%1}, [%2];"
                 : "=r"(r0), "=r"(r1) : "r"(addr));
}
__device__ __forceinline__ void mma16816(float* c, const uint32_t* a, uint32_t b0, uint32_t b1) {
    asm volatile(
        "mma.sync.aligned.m16n8k16.row.col.f32.bf16.bf16.f32 "
        "{%0,%1,%2,%3}, {%4,%5,%6,%7}, {%8,%9}, {%0,%1,%2,%3};"
        : "+f"(c[0]), "+f"(c[1]), "+f"(c[2]), "+f"(c[3])
        : "r"(a[0]), "r"(a[1]), "r"(a[2]), "r"(a[3]), "r"(b0), "r"(b1));
}
__device__ __forceinline__ void split_bf16(float v, __nv_bfloat16& h, __nv_bfloat16& l) {
    h = __float2bfloat16(v);
    l = __float2bfloat16(v - __bfloat162float(h));
}

// ---------------- prep ----------------
__global__ void prep_kernel(const float* __restrict__ W1, const float* __restrict__ b1,
                            const float* __restrict__ W_ih, const float* __restrict__ b_ih) {
    int bid = blockIdx.x, tid = threadIdx.x;
    __shared__ float wih[DIM];
    __shared__ float red[DIM];
    wih[tid] = W_ih[bid * DIM + tid];
    __syncthreads();
    float acc = 0.f;
    #pragma unroll 8
    for (int k = 0; k < DIM; k++)
        acc = fmaf(wih[k], W1[k * DIM + tid], acc);
    __nv_bfloat16 h, l;
    split_bf16(acc, h, l);
    g_Bh[bid * DIM + tid] = h;
    g_Bl[bid * DIM + tid] = l;
    red[tid] = wih[tid] * b1[tid];
    __syncthreads();
    if (tid == 0) {
        float s = 0.f;
        for (int k = 0; k < DIM; k++) s += red[k];
        g_bc[bid] = s + b_ih[bid];
    }
}

// ---------------- HMMA GI GEMM v2: resident B, 4 m-tiles/block ----------------
// grid (3, 1024): nt fastest (A L2 reuse). Block: B hi/lo staged once; loop over
// 4 m-tiles of 128 rows, A prefetched to regs during previous tile's mma.
// Warp tile 64x32 (2m x 4n warps, mf=4) amortizes B-side ldsm.
#define G2_BC   0
#define G2_BH   1024
#define G2_BL   (G2_BH + 34816)
#define G2_AH   (G2_BL + 34816)
#define G2_AL   (G2_AH + 34816)
#define G2SMEM  (G2_AL + 34816)          // 140288 B
#define MTPB    4

__global__ __launch_bounds__(256, 1)
void gi_gemm_hmma(const float* __restrict__ X) {
    extern __shared__ char smem[];
    const uint32_t sbase = smem_u32(smem);
    const int tid = threadIdx.x;
    const int wid = tid >> 5, lane = tid & 31;
    const int nt = blockIdx.x;
    const int n0 = nt * 128;
    const int mbase = blockIdx.y * (MTPB * 128);

    // stage B (hi/lo) + bc once
    const uint4* Bh4 = (const uint4*)(g_Bh + nt * 16384);
    const uint4* Bl4 = (const uint4*)(g_Bl + nt * 16384);
    #pragma unroll 4
    for (int s = tid; s < 2048; s += 256) {
        int row = s >> 4, u = s & 15;
        int off = row * 272 + u * 16;
        *(uint4*)(smem + G2_BH + off) = Bh4[s];
        *(uint4*)(smem + G2_BL + off) = Bl4[s];
    }
    if (tid < 128) *(float*)(smem + G2_BC + tid * 4) = g_bc[n0 + tid];

    // prefetch A tile 0 (fp32 -> regs)
    float4 apre[16];
    {
        const float4* Xf4 = (const float4*)X;
        #pragma unroll
        for (int it = 0; it < 16; it++)
            apre[it] = Xf4[(size_t)mbase * 32 + it * 256 + tid];
    }
    __syncthreads();

    // warp tiling: 2 (m) x 4 (n); warp tile 64x32
    const int wm = wid & 1;
    const int wn = wid >> 1;
    const uint32_t aoff = (uint32_t)(wm * 64 + (lane & 15)) * 272 + ((lane >> 4) << 4);
    const uint32_t boff = (uint32_t)(wn * 32 + (lane & 7) + ((lane >> 4) << 3)) * 272
                        + (((lane >> 3) & 1) << 4);
    const float* bcs = (const float*)(smem + G2_BC);
    const int qrow = lane >> 2, qcol = (lane & 3) * 2;

    for (int i = 0; i < MTPB; i++) {
        const int m0 = mbase + i * 128;
        if (i > 0) __syncthreads();           // prior tile's ldsm reads complete

        // convert + STS A from prefetch regs
        #pragma unroll
        for (int it = 0; it < 16; it++) {
            int s = it * 256 + tid;
            int row = s >> 5, q = s & 31;
            float4 v = apre[it];
            __nv_bfloat16 h0, h1, h2, h3, l0, l1, l2, l3;
            split_bf16(v.x, h0, l0); split_bf16(v.y, h1, l1);
            split_bf16(v.z, h2, l2); split_bf16(v.w, h3, l3);
            __nv_bfloat162 hA(h0, h1), hB(h2, h3), lA(l0, l1), lB(l2, l3);
            int off = row * 272 + q * 8;
            *(uint2*)(smem + G2_AH + off) = make_uint2(*(uint32_t*)&hA, *(uint32_t*)&hB);
            *(uint2*)(smem + G2_AL + off) = make_uint2(*(uint32_t*)&lA, *(uint32_t*)&lB);
        }
        // prefetch next tile during this tile's mma
        if (i + 1 < MTPB) {
            const float4* Xf4 = (const float4*)X;
            #pragma unroll
            for (int it = 0; it < 16; it++)
                apre[it] = Xf4[(size_t)(m0 + 128) * 32 + it * 256 + tid];
        }
        __syncthreads();                      // A(i) visible

        float C[4][4][4];
        #pragma unroll
        for (int mf = 0; mf < 4; mf++)
            #pragma unroll
            for (int nf = 0; nf < 4; nf++)
                #pragma unroll
                for (int q = 0; q < 4; q++) C[mf][nf][q] = 0.f;

        const uint32_t abase2[3] = { sbase + G2_AH, sbase + G2_AH, sbase + G2_AL };
        const uint32_t bbase2[3] = { sbase + G2_BH, sbase + G2_BL, sbase + G2_BH };

        #pragma unroll
        for (int p = 0; p < 3; p++) {
            const uint32_t ab = abase2[p] + aoff;
            const uint32_t bb = bbase2[p] + boff;
            #pragma unroll
            for (int ks = 0; ks < 8; ks++) {
                uint32_t b0f[4], b1f[4];
                ldsm4(b0f[0], b0f[1], b0f[2], b0f[3], bb + ks * 32);
                ldsm4(b1f[0], b1f[1], b1f[2], b1f[3], bb + 16 * 272 + ks * 32);
                #pragma unroll
                for (int mf = 0; mf < 4; mf++) {
                    uint32_t a[4];
                    ldsm4(a[0], a[1], a[2], a[3], ab + mf * (16 * 272) + ks * 32);
                    mma16816(C[mf][0], a, b0f[0], b0f[1]);
                    mma16816(C[mf][1], a, b0f[2], b0f[3]);
                    mma16816(C[mf][2], a, b1f[0], b1f[1]);
                    mma16816(C[mf][3], a, b1f[2], b1f[3]);
                }
            }
        }

        // epilogue: add bc, store
        #pragma unroll
        for (int mf = 0; mf < 4; mf++) {
            int row = m0 + wm * 64 + mf * 16 + qrow;
            #pragma unroll
            for (int nf = 0; nf < 4; nf++) {
                int colL = wn * 32 + nf * 8 + qcol;
                float b0 = bcs[colL], b1 = bcs[colL + 1];
                float* d0 = g_GI + (size_t)row * GATES + n0 + colL;
                *(float2*)d0 = make_float2(C[mf][nf][0] + b0, C[mf][nf][1] + b1);
                float* d1 = g_GI + (size_t)(row + 8) * GATES + n0 + colL;
                *(float2*)d1 = make_float2(C[mf][nf][2] + b0, C[mf][nf][3] + b1);
            }
        }
    }
}

// ---------------- HMMA GRU scan v7 (unchanged from R11) ----------------
#define VW_LO   0
#define VW_HI   104448
#define VH      0
#define VBH     4096
#define VSMEM   (104448 * 2)

__global__ __launch_bounds__(256, 1)
void gru_scan_hmma(const float* __restrict__ W_hh, const float* __restrict__ b_hh,
                   float* __restrict__ out) {
    extern __shared__ char smem[];
    const uint32_t sbase = smem_u32(smem);
    const int tid = threadIdx.x, w = tid >> 5, lane = tid & 31;
    const int r0 = blockIdx.x * 4;

    #pragma unroll 4
    for (int s = tid; s < 12288; s += 256) {
        int row = s >> 5, q = s & 31;
        float4 v = ((const float4*)W_hh)[s];
        __nv_bfloat16 h0, h1, h2, h3, l0, l1, l2, l3;
        split_bf16(v.x, h0, l0); split_bf16(v.y, h1, l1);
        split_bf16(v.z, h2, l2); split_bf16(v.w, h3, l3);
        __nv_bfloat162 hA(h0, h1), hB(h2, h3), lA(l0, l1), lB(l2, l3);
        int off = row * 272 + q * 8;
        *(uint2*)(smem + VW_HI + off) = make_uint2(*(uint32_t*)&hA, *(uint32_t*)&hB);
        *(uint2*)(smem + VW_LO + off) = make_uint2(*(uint32_t*)&lA, *(uint32_t*)&lB);
    }
    __syncthreads();

    uint32_t wh[3][8][4], wl[3][8][4];
    {
        const uint32_t lo_off = (uint32_t)(16 * w + (lane & 15)) * 272 + ((lane >> 4) << 4);
        #pragma unroll
        for (int g = 0; g < 3; g++)
            #pragma unroll
            for (int ks = 0; ks < 8; ks++) {
                ldsm4(wh[g][ks][0], wh[g][ks][1], wh[g][ks][2], wh[g][ks][3],
                      sbase + VW_HI + lo_off + (uint32_t)g * (128 * 272) + ks * 32);
                ldsm4(wl[g][ks][0], wl[g][ks][1], wl[g][ks][2], wl[g][ks][3],
                      sbase + VW_LO + lo_off + (uint32_t)g * (128 * 272) + ks * 32);
            }
    }
    __syncthreads();

    for (int s = tid; s < 512; s += 256)
        ((uint32_t*)(smem + VH))[s] = 0;
    for (int s = tid; s < GATES; s += 256)
        *(float*)(smem + VBH + s * 4) = b_hh[s];
    __syncthreads();

    const int jq = lane >> 2;
    const int j0 = 16 * w + jq, j1 = j0 + 8;
    const int bsel = lane & 3;
    const bool valid = (bsel < 2);
    const int b0 = 2 * bsel;

    const uint32_t bfb = sbase + VH + (uint32_t)(lane & 15) * 16;
    const float* bhs = (const float*)(smem + VBH);

    float hprev[4] = {0.f, 0.f, 0.f, 0.f};

    for (int t = 0; t < T_STEPS; t++) {
        const int cur = t & 1;

        float giv[3][4];
        #pragma unroll
        for (int q = 0; q < 4; q++) {
            if (valid) {
                int j = (q & 2) ? j1 : j0;
                int b = b0 + (q & 1);
                size_t base = ((size_t)t * BATCH + r0 + b) * GATES + j;
                giv[0][q] = g_GI[base];
                giv[1][q] = g_GI[base + DIM];
                giv[2][q] = g_GI[base + 2 * DIM];
            } else {
                giv[0][q] = giv[1][q] = giv[2][q] = 0.f;
            }
        }

        float Ch[3][4], Cl[3][4];
        #pragma unroll
        for (int g = 0; g < 3; g++)
            #pragma unroll
            for (int q = 0; q < 4; q++) { Ch[g][q] = 0.f; Cl[g][q] = 0.f; }

        const uint32_t hb = bfb + (uint32_t)cur * 2048;
        uint32_t bf0, bf1;
        ldsm2t(bf0, bf1, hb);
        #pragma unroll
        for (int ks = 0; ks < 8; ks++) {
            uint32_t nf0 = 0, nf1 = 0;
            if (ks < 7) ldsm2t(nf0, nf1, hb + (ks + 1) * 256);
            mma16816(Ch[0], wh[0][ks], bf0, bf1);
            mma16816(Ch[1], wh[1][ks], bf0, bf1);
            mma16816(Ch[2], wh[2][ks], bf0, bf1);
            mma16816(Cl[0], wl[0][ks], bf0, bf1);
            mma16816(Cl[1], wl[1][ks], bf0, bf1);
            mma16816(Cl[2], wl[2][ks], bf0, bf1);
            bf0 = nf0; bf1 = nf1;
        }

        float hnew[4];
        #pragma unroll
        for (int q = 0; q < 4; q++) {
            float gr = Ch[0][q] + Cl[0][q]; gr += __shfl_xor_sync(0xffffffffu, gr, 2);
            float gz = Ch[1][q] + Cl[1][q]; gz += __shfl_xor_sync(0xffffffffu, gz, 2);
            float gn = Ch[2][q] + Cl[2][q]; gn += __shfl_xor_sync(0xffffffffu, gn, 2);
            int j = (q & 2) ? j1 : j0;
            float r = sigm_fast(gr + bhs[j] + giv[0][q]);
            float z = sigm_fast(gz + bhs[DIM + j] + giv[1][q]);
            float n = tanhf_fast(giv[2][q] + r * (gn + bhs[2 * DIM + j]));
            hnew[q] = n + z * (hprev[q] - n);
            hprev[q] = hnew[q];
        }
        if (valid) {
            const uint32_t nb = VH + (uint32_t)(cur ^ 1) * 2048;
            #pragma unroll
            for (int q = 0; q < 4; q++) {
                int j = (q & 2) ? j1 : j0;
                int b = b0 + (q & 1);
                __nv_bfloat16 hh, hl;
                split_bf16(hnew[q], hh, hl);
                *(__nv_bfloat16*)(smem + nb + j * 16 + b * 2) = hh;
                *(__nv_bfloat16*)(smem + nb + j * 16 + 8 + b * 2) = hl;
            }
        }
        __syncthreads();
    }

    if (valid) {
        #pragma unroll
        for (int q = 0; q < 4; q++) {
            int j = (q & 2) ? j1 : j0;
            int b = b0 + (q & 1);
            out[(r0 + b) * DIM + j] = hprev[q];
        }
    }
}

// ---------------- launch ----------------
extern "C" void kernel_launch(void* const* d_in, const int* in_sizes, int n_in,
                              void* d_out, int out_size) {
    const float* x    = (const float*)d_in[0];
    const float* W1   = (const float*)d_in[1];
    const float* b1   = (const float*)d_in[2];
    const float* W_ih = (const float*)d_in[3];
    const float* W_hh = (const float*)d_in[4];
    const float* b_ih = (const float*)d_in[5];
    const float* b_hh = (const float*)d_in[6];
    float* out = (float*)d_out;

    static bool attr_done = false;
    if (!attr_done) {
        cudaFuncSetAttribute(gi_gemm_hmma,
                             cudaFuncAttributeMaxDynamicSharedMemorySize, G2SMEM);
        cudaFuncSetAttribute(gru_scan_hmma,
                             cudaFuncAttributeMaxDynamicSharedMemorySize, VSMEM);
        attr_done = true;
    }

    prep_kernel<<<GATES, DIM>>>(W1, b1, W_ih, b_ih);
    gi_gemm_hmma<<<dim3(3, 1024), 256, G2SMEM>>>(x);
    gru_scan_hmma<<<128, 256, VSMEM>>>(W_hh, b_hh, out);
}

// round 14
// speedup vs baseline: 1.5281x; 1.5281x over previous
#include <cuda_runtime.h>
#include <cuda_bf16.h>
#include <cstdint>

#define T_STEPS 1024
#define BATCH   512
#define DIM     128
#define GATES   384

// ---------------- device scratch ----------------
__device__ float g_bc[GATES];
__device__ __nv_bfloat16 g_Bh[3 * 16384];                // Wc hi: [nt][row][k]
__device__ __nv_bfloat16 g_Bl[3 * 16384];                // Wc lo
__device__ float g_GI[(size_t)T_STEPS * BATCH * GATES];  // 805 MB scratch

// ---------------- helpers ----------------
__device__ __forceinline__ float tanhf_fast(float x) {
    float y; asm("tanh.approx.f32 %0, %1;" : "=f"(y) : "f"(x)); return y;
}
__device__ __forceinline__ float sigm_fast(float x) {
    return fmaf(0.5f, tanhf_fast(0.5f * x), 0.5f);
}
__device__ __forceinline__ uint32_t smem_u32(const void* p) {
    uint32_t a;
    asm("{ .reg .u64 t; cvta.to.shared.u64 t, %1; cvt.u32.u64 %0, t; }" : "=r"(a) : "l"(p));
    return a;
}
__device__ __forceinline__ void ldsm4(uint32_t& r0, uint32_t& r1, uint32_t& r2, uint32_t& r3,
                                      uint32_t addr) {
    asm volatile("ldmatrix.sync.aligned.m8n8.x4.shared.b16 {%0,%1,%2,%3}, [%4];"
                 : "=r"(r0), "=r"(r1), "=r"(r2), "=r"(r3) : "r"(addr));
}
__device__ __forceinline__ void ldsm2t(uint32_t& r0, uint32_t& r1, uint32_t addr) {
    asm volatile("ldmatrix.sync.aligned.m8n8.x2.trans.shared.b16 {%0,%1}, [%2];"
                 : "=r"(r0), "=r"(r1) : "r"(addr));
}
__device__ __forceinline__ void mma16816(float* c, const uint32_t* a, uint32_t b0, uint32_t b1) {
    asm volatile(
        "mma.sync.aligned.m16n8k16.row.col.f32.bf16.bf16.f32 "
        "{%0,%1,%2,%3}, {%4,%5,%6,%7}, {%8,%9}, {%0,%1,%2,%3};"
        : "+f"(c[0]), "+f"(c[1]), "+f"(c[2]), "+f"(c[3])
        : "r"(a[0]), "r"(a[1]), "r"(a[2]), "r"(a[3]), "r"(b0), "r"(b1));
}
__device__ __forceinline__ void split_bf16(float v, __nv_bfloat16& h, __nv_bfloat16& l) {
    h = __float2bfloat16(v);
    l = __float2bfloat16(v - __bfloat162float(h));
}

// ---------------- prep ----------------
__global__ void prep_kernel(const float* __restrict__ W1, const float* __restrict__ b1,
                            const float* __restrict__ W_ih, const float* __restrict__ b_ih) {
    int bid = blockIdx.x, tid = threadIdx.x;
    __shared__ float wih[DIM];
    __shared__ float red[DIM];
    wih[tid] = W_ih[bid * DIM + tid];
    __syncthreads();
    float acc = 0.f;
    #pragma unroll 8
    for (int k = 0; k < DIM; k++)
        acc = fmaf(wih[k], W1[k * DIM + tid], acc);
    __nv_bfloat16 h, l;
    split_bf16(acc, h, l);
    g_Bh[bid * DIM + tid] = h;
    g_Bl[bid * DIM + tid] = l;
    red[tid] = wih[tid] * b1[tid];
    __syncthreads();
    if (tid == 0) {
        float s = 0.f;
        for (int k = 0; k < DIM; k++) s += red[k];
        g_bc[bid] = s + b_ih[bid];
    }
}

// ---------------- HMMA GI GEMM v3: R11 tile shape + resident B ----------------
// grid (3, 1024): block stages B hi/lo + bc ONCE, then loops 8 m-tiles of 64 rows
// with R11's exact warp tiling (2m x 4n, warp tile 32x32, C[2][4][4]). occ 2.
#define G3_BC   0
#define G3_BH   1024
#define G3_BL   (G3_BH + 34816)
#define G3_AH   (G3_BL + 34816)
#define G3_AL   (G3_AH + 17408)
#define G3SMEM  (G3_AL + 17408)          // 105472 B -> occ 2
#define MT3     8

__global__ __launch_bounds__(256, 2)
void gi_gemm_hmma(const float* __restrict__ X) {
    extern __shared__ char smem[];
    const uint32_t sbase = smem_u32(smem);
    const int tid = threadIdx.x;
    const int wid = tid >> 5, lane = tid & 31;
    const int nt = blockIdx.x;
    const int n0 = nt * 128;
    const int mbase = blockIdx.y * (MT3 * 64);

    // stage B (hi/lo) + bc once per block
    const uint4* Bh4 = (const uint4*)(g_Bh + nt * 16384);
    const uint4* Bl4 = (const uint4*)(g_Bl + nt * 16384);
    #pragma unroll 4
    for (int s = tid; s < 2048; s += 256) {
        int row = s >> 4, u = s & 15;
        int off = row * 272 + u * 16;
        *(uint4*)(smem + G3_BH + off) = Bh4[s];
        *(uint4*)(smem + G3_BL + off) = Bl4[s];
    }
    if (tid < 128) *(float*)(smem + G3_BC + tid * 4) = g_bc[n0 + tid];
    __syncthreads();

    const int wm = wid & 1;
    const int wn = wid >> 1;
    const uint32_t aoff = (uint32_t)(wm * 32 + (lane & 15)) * 272 + ((lane >> 4) << 4);
    const uint32_t boff = (uint32_t)(wn * 32 + (lane & 7) + ((lane >> 4) << 3)) * 272
                        + (((lane >> 3) & 1) << 4);
    const float* bcs = (const float*)(smem + G3_BC);
    const int qrow = lane >> 2, qcol = (lane & 3) * 2;

    const uint32_t abase[3] = { sbase + G3_AH, sbase + G3_AH, sbase + G3_AL };
    const uint32_t bbase[3] = { sbase + G3_BH, sbase + G3_BL, sbase + G3_BH };

    for (int i = 0; i < MT3; i++) {
        const int m0 = mbase + i * 64;
        if (i > 0) __syncthreads();      // previous tile's A ldsm reads complete

        // stage A tile (fp32 -> bf16 hi/lo)
        const float4* Xf4 = (const float4*)X;
        #pragma unroll 4
        for (int s = tid; s < 2048; s += 256) {
            int row = s >> 5, q = s & 31;
            float4 v = Xf4[(size_t)(m0 + row) * 32 + q];
            __nv_bfloat16 h0, h1, h2, h3, l0, l1, l2, l3;
            split_bf16(v.x, h0, l0); split_bf16(v.y, h1, l1);
            split_bf16(v.z, h2, l2); split_bf16(v.w, h3, l3);
            __nv_bfloat162 hA(h0, h1), hB(h2, h3), lA(l0, l1), lB(l2, l3);
            int off = row * 272 + q * 8;
            *(uint2*)(smem + G3_AH + off) = make_uint2(*(uint32_t*)&hA, *(uint32_t*)&hB);
            *(uint2*)(smem + G3_AL + off) = make_uint2(*(uint32_t*)&lA, *(uint32_t*)&lB);
        }
        __syncthreads();

        float C[2][4][4];
        #pragma unroll
        for (int mf = 0; mf < 2; mf++)
            #pragma unroll
            for (int nf = 0; nf < 4; nf++)
                #pragma unroll
                for (int q = 0; q < 4; q++) C[mf][nf][q] = 0.f;

        #pragma unroll
        for (int p = 0; p < 3; p++) {
            const uint32_t ab = abase[p] + aoff;
            const uint32_t bb = bbase[p] + boff;
            #pragma unroll
            for (int ks = 0; ks < 8; ks++) {
                uint32_t a[2][4], b[2][4];
                ldsm4(a[0][0], a[0][1], a[0][2], a[0][3], ab + ks * 32);
                ldsm4(a[1][0], a[1][1], a[1][2], a[1][3], ab + 16 * 272 + ks * 32);
                ldsm4(b[0][0], b[0][1], b[0][2], b[0][3], bb + ks * 32);
                ldsm4(b[1][0], b[1][1], b[1][2], b[1][3], bb + 16 * 272 + ks * 32);
                #pragma unroll
                for (int mf = 0; mf < 2; mf++) {
                    mma16816(C[mf][0], a[mf], b[0][0], b[0][1]);
                    mma16816(C[mf][1], a[mf], b[0][2], b[0][3]);
                    mma16816(C[mf][2], a[mf], b[1][0], b[1][1]);
                    mma16816(C[mf][3], a[mf], b[1][2], b[1][3]);
                }
            }
        }

        #pragma unroll
        for (int mf = 0; mf < 2; mf++) {
            int row = m0 + wm * 32 + mf * 16 + qrow;
            #pragma unroll
            for (int nf = 0; nf < 4; nf++) {
                int colL = wn * 32 + nf * 8 + qcol;
                float b0 = bcs[colL], b1 = bcs[colL + 1];
                float* d0 = g_GI + (size_t)row * GATES + n0 + colL;
                *(float2*)d0 = make_float2(C[mf][nf][0] + b0, C[mf][nf][1] + b1);
                float* d1 = g_GI + (size_t)(row + 8) * GATES + n0 + colL;
                *(float2*)d1 = make_float2(C[mf][nf][2] + b0, C[mf][nf][3] + b1);
            }
        }
    }
}

// ---------------- HMMA GRU scan v7 (unchanged from R11) ----------------
#define VW_LO   0
#define VW_HI   104448
#define VH      0
#define VBH     4096
#define VSMEM   (104448 * 2)

__global__ __launch_bounds__(256, 1)
void gru_scan_hmma(const float* __restrict__ W_hh, const float* __restrict__ b_hh,
                   float* __restrict__ out) {
    extern __shared__ char smem[];
    const uint32_t sbase = smem_u32(smem);
    const int tid = threadIdx.x, w = tid >> 5, lane = tid & 31;
    const int r0 = blockIdx.x * 4;

    #pragma unroll 4
    for (int s = tid; s < 12288; s += 256) {
        int row = s >> 5, q = s & 31;
        float4 v = ((const float4*)W_hh)[s];
        __nv_bfloat16 h0, h1, h2, h3, l0, l1, l2, l3;
        split_bf16(v.x, h0, l0); split_bf16(v.y, h1, l1);
        split_bf16(v.z, h2, l2); split_bf16(v.w, h3, l3);
        __nv_bfloat162 hA(h0, h1), hB(h2, h3), lA(l0, l1), lB(l2, l3);
        int off = row * 272 + q * 8;
        *(uint2*)(smem + VW_HI + off) = make_uint2(*(uint32_t*)&hA, *(uint32_t*)&hB);
        *(uint2*)(smem + VW_LO + off) = make_uint2(*(uint32_t*)&lA, *(uint32_t*)&lB);
    }
    __syncthreads();

    uint32_t wh[3][8][4], wl[3][8][4];
    {
        const uint32_t lo_off = (uint32_t)(16 * w + (lane & 15)) * 272 + ((lane >> 4) << 4);
        #pragma unroll
        for (int g = 0; g < 3; g++)
            #pragma unroll
            for (int ks = 0; ks < 8; ks++) {
                ldsm4(wh[g][ks][0], wh[g][ks][1], wh[g][ks][2], wh[g][ks][3],
                      sbase + VW_HI + lo_off + (uint32_t)g * (128 * 272) + ks * 32);
                ldsm4(wl[g][ks][0], wl[g][ks][1], wl[g][ks][2], wl[g][ks][3],
                      sbase + VW_LO + lo_off + (uint32_t)g * (128 * 272) + ks * 32);
            }
    }
    __syncthreads();

    for (int s = tid; s < 512; s += 256)
        ((uint32_t*)(smem + VH))[s] = 0;
    for (int s = tid; s < GATES; s += 256)
        *(float*)(smem + VBH + s * 4) = b_hh[s];
    __syncthreads();

    const int jq = lane >> 2;
    const int j0 = 16 * w + jq, j1 = j0 + 8;
    const int bsel = lane & 3;
    const bool valid = (bsel < 2);
    const int b0 = 2 * bsel;

    const uint32_t bfb = sbase + VH + (uint32_t)(lane & 15) * 16;
    const float* bhs = (const float*)(smem + VBH);

    float hprev[4] = {0.f, 0.f, 0.f, 0.f};

    for (int t = 0; t < T_STEPS; t++) {
        const int cur = t & 1;

        float giv[3][4];
        #pragma unroll
        for (int q = 0; q < 4; q++) {
            if (valid) {
                int j = (q & 2) ? j1 : j0;
                int b = b0 + (q & 1);
                size_t base = ((size_t)t * BATCH + r0 + b) * GATES + j;
                giv[0][q] = g_GI[base];
                giv[1][q] = g_GI[base + DIM];
                giv[2][q] = g_GI[base + 2 * DIM];
            } else {
                giv[0][q] = giv[1][q] = giv[2][q] = 0.f;
            }
        }

        float Ch[3][4], Cl[3][4];
        #pragma unroll
        for (int g = 0; g < 3; g++)
            #pragma unroll
            for (int q = 0; q < 4; q++) { Ch[g][q] = 0.f; Cl[g][q] = 0.f; }

        const uint32_t hb = bfb + (uint32_t)cur * 2048;
        uint32_t bf0, bf1;
        ldsm2t(bf0, bf1, hb);
        #pragma unroll
        for (int ks = 0; ks < 8; ks++) {
            uint32_t nf0 = 0, nf1 = 0;
            if (ks < 7) ldsm2t(nf0, nf1, hb + (ks + 1) * 256);
            mma16816(Ch[0], wh[0][ks], bf0, bf1);
            mma16816(Ch[1], wh[1][ks], bf0, bf1);
            mma16816(Ch[2], wh[2][ks], bf0, bf1);
            mma16816(Cl[0], wl[0][ks], bf0, bf1);
            mma16816(Cl[1], wl[1][ks], bf0, bf1);
            mma16816(Cl[2], wl[2][ks], bf0, bf1);
            bf0 = nf0; bf1 = nf1;
        }

        float hnew[4];
        #pragma unroll
        for (int q = 0; q < 4; q++) {
            float gr = Ch[0][q] + Cl[0][q]; gr += __shfl_xor_sync(0xffffffffu, gr, 2);
            float gz = Ch[1][q] + Cl[1][q]; gz += __shfl_xor_sync(0xffffffffu, gz, 2);
            float gn = Ch[2][q] + Cl[2][q]; gn += __shfl_xor_sync(0xffffffffu, gn, 2);
            int j = (q & 2) ? j1 : j0;
            float r = sigm_fast(gr + bhs[j] + giv[0][q]);
            float z = sigm_fast(gz + bhs[DIM + j] + giv[1][q]);
            float n = tanhf_fast(giv[2][q] + r * (gn + bhs[2 * DIM + j]));
            hnew[q] = n + z * (hprev[q] - n);
            hprev[q] = hnew[q];
        }
        if (valid) {
            const uint32_t nb = VH + (uint32_t)(cur ^ 1) * 2048;
            #pragma unroll
            for (int q = 0; q < 4; q++) {
                int j = (q & 2) ? j1 : j0;
                int b = b0 + (q & 1);
                __nv_bfloat16 hh, hl;
                split_bf16(hnew[q], hh, hl);
                *(__nv_bfloat16*)(smem + nb + j * 16 + b * 2) = hh;
                *(__nv_bfloat16*)(smem + nb + j * 16 + 8 + b * 2) = hl;
            }
        }
        __syncthreads();
    }

    if (valid) {
        #pragma unroll
        for (int q = 0; q < 4; q++) {
            int j = (q & 2) ? j1 : j0;
            int b = b0 + (q & 1);
            out[(r0 + b) * DIM + j] = hprev[q];
        }
    }
}

// ---------------- launch ----------------
extern "C" void kernel_launch(void* const* d_in, const int* in_sizes, int n_in,
                              void* d_out, int out_size) {
    const float* x    = (const float*)d_in[0];
    const float* W1   = (const float*)d_in[1];
    const float* b1   = (const float*)d_in[2];
    const float* W_ih = (const float*)d_in[3];
    const float* W_hh = (const float*)d_in[4];
    const float* b_ih = (const float*)d_in[5];
    const float* b_hh = (const float*)d_in[6];
    float* out = (float*)d_out;

    static bool attr_done = false;
    if (!attr_done) {
        cudaFuncSetAttribute(gi_gemm_hmma,
                             cudaFuncAttributeMaxDynamicSharedMemorySize, G3SMEM);
        cudaFuncSetAttribute(gru_scan_hmma,
                             cudaFuncAttributeMaxDynamicSharedMemorySize, VSMEM);
        attr_done = true;
    }

    prep_kernel<<<GATES, DIM>>>(W1, b1, W_ih, b_ih);
    gi_gemm_hmma<<<dim3(3, 1024), 256, G3SMEM>>>(x);
    gru_scan_hmma<<<128, 256, VSMEM>>>(W_hh, b_hh, out);
}

// round 15
// speedup vs baseline: 1.7939x; 1.1739x over previous
#include <cuda_runtime.h>
#include <cuda_bf16.h>
#include <cuda_fp16.h>
#include <cstdint>

#define T_STEPS 1024
#define BATCH   512
#define DIM     128
#define GATES   384

// ---------------- device scratch ----------------
__device__ float g_bc[GATES];
__device__ __half g_Wc16[3 * 16384];                     // Wc fp16: [nt][row][k]
__device__ float g_GI[(size_t)T_STEPS * BATCH * GATES];  // 805 MB scratch

// ---------------- helpers ----------------
__device__ __forceinline__ float tanhf_fast(float x) {
    float y; asm("tanh.approx.f32 %0, %1;" : "=f"(y) : "f"(x)); return y;
}
__device__ __forceinline__ float sigm_fast(float x) {
    return fmaf(0.5f, tanhf_fast(0.5f * x), 0.5f);
}
__device__ __forceinline__ uint32_t smem_u32(const void* p) {
    uint32_t a;
    asm("{ .reg .u64 t; cvta.to.shared.u64 t, %1; cvt.u32.u64 %0, t; }" : "=r"(a) : "l"(p));
    return a;
}
__device__ __forceinline__ void ldsm4(uint32_t& r0, uint32_t& r1, uint32_t& r2, uint32_t& r3,
                                      uint32_t addr) {
    asm volatile("ldmatrix.sync.aligned.m8n8.x4.shared.b16 {%0,%1,%2,%3}, [%4];"
                 : "=r"(r0), "=r"(r1), "=r"(r2), "=r"(r3) : "r"(addr));
}
__device__ __forceinline__ void ldsm2t(uint32_t& r0, uint32_t& r1, uint32_t addr) {
    asm volatile("ldmatrix.sync.aligned.m8n8.x2.trans.shared.b16 {%0,%1}, [%2];"
                 : "=r"(r0), "=r"(r1) : "r"(addr));
}
// bf16 mma (scan)
__device__ __forceinline__ void mma16816(float* c, const uint32_t* a, uint32_t b0, uint32_t b1) {
    asm volatile(
        "mma.sync.aligned.m16n8k16.row.col.f32.bf16.bf16.f32 "
        "{%0,%1,%2,%3}, {%4,%5,%6,%7}, {%8,%9}, {%0,%1,%2,%3};"
        : "+f"(c[0]), "+f"(c[1]), "+f"(c[2]), "+f"(c[3])
        : "r"(a[0]), "r"(a[1]), "r"(a[2]), "r"(a[3]), "r"(b0), "r"(b1));
}
// fp16 mma (GEMM)
__device__ __forceinline__ void mma16816h(float* c, const uint32_t* a, uint32_t b0, uint32_t b1) {
    asm volatile(
        "mma.sync.aligned.m16n8k16.row.col.f32.f16.f16.f32 "
        "{%0,%1,%2,%3}, {%4,%5,%6,%7}, {%8,%9}, {%0,%1,%2,%3};"
        : "+f"(c[0]), "+f"(c[1]), "+f"(c[2]), "+f"(c[3])
        : "r"(a[0]), "r"(a[1]), "r"(a[2]), "r"(a[3]), "r"(b0), "r"(b1));
}
__device__ __forceinline__ void split_bf16(float v, __nv_bfloat16& h, __nv_bfloat16& l) {
    h = __float2bfloat16(v);
    l = __float2bfloat16(v - __bfloat162float(h));
}
__device__ __forceinline__ void split_fp16(float v, __half& h, __half& l) {
    h = __float2half_rn(v);
    l = __float2half_rn(v - __half2float(h));
}

// ---------------- prep: fold fc1 into Wc (fp16) + bc ----------------
__global__ void prep_kernel(const float* __restrict__ W1, const float* __restrict__ b1,
                            const float* __restrict__ W_ih, const float* __restrict__ b_ih) {
    int bid = blockIdx.x, tid = threadIdx.x;
    __shared__ float wih[DIM];
    __shared__ float red[DIM];
    wih[tid] = W_ih[bid * DIM + tid];
    __syncthreads();
    float acc = 0.f;
    #pragma unroll 8
    for (int k = 0; k < DIM; k++)
        acc = fmaf(wih[k], W1[k * DIM + tid], acc);
    g_Wc16[bid * DIM + tid] = __float2half_rn(acc);
    red[tid] = wih[tid] * b1[tid];
    __syncthreads();
    if (tid == 0) {
        float s = 0.f;
        for (int k = 0; k < DIM; k++) s += red[k];
        g_bc[bid] = s + b_ih[bid];
    }
}

// ---------------- HMMA GI GEMM v4: fp16 2-pass, resident B ----------------
// grid (3, 1024). Block: B (single fp16) + bc staged once; 8 m-tiles of 64 rows.
// GI = Xh*W + Xl*W (X split to fp16 hi/lo; W single fp16). occ 2.
#define G4_BC   0
#define G4_B    1024
#define G4_AH   (G4_B + 34816)
#define G4_AL   (G4_AH + 17408)
#define G4SMEM  (G4_AL + 17408)          // 70656 B -> occ 2 (smem), reg-capped 2
#define MT4     8

__global__ __launch_bounds__(256, 2)
void gi_gemm_hmma(const float* __restrict__ X) {
    extern __shared__ char smem[];
    const uint32_t sbase = smem_u32(smem);
    const int tid = threadIdx.x;
    const int wid = tid >> 5, lane = tid & 31;
    const int nt = blockIdx.x;
    const int n0 = nt * 128;
    const int mbase = blockIdx.y * (MT4 * 64);

    // stage B (fp16) + bc once per block
    const uint4* B4 = (const uint4*)(g_Wc16 + nt * 16384);
    #pragma unroll 4
    for (int s = tid; s < 2048; s += 256) {
        int row = s >> 4, u = s & 15;
        *(uint4*)(smem + G4_B + row * 272 + u * 16) = B4[s];
    }
    if (tid < 128) *(float*)(smem + G4_BC + tid * 4) = g_bc[n0 + tid];
    __syncthreads();

    const int wm = wid & 1;
    const int wn = wid >> 1;
    const uint32_t aoff = (uint32_t)(wm * 32 + (lane & 15)) * 272 + ((lane >> 4) << 4);
    const uint32_t boff = (uint32_t)(wn * 32 + (lane & 7) + ((lane >> 4) << 3)) * 272
                        + (((lane >> 3) & 1) << 4);
    const float* bcs = (const float*)(smem + G4_BC);
    const int qrow = lane >> 2, qcol = (lane & 3) * 2;

    const uint32_t abase[2] = { sbase + G4_AH, sbase + G4_AL };
    const uint32_t bb = sbase + G4_B + boff;

    for (int i = 0; i < MT4; i++) {
        const int m0 = mbase + i * 64;
        if (i > 0) __syncthreads();      // previous tile's A ldsm reads complete

        // stage A tile (fp32 -> fp16 hi/lo)
        const float4* Xf4 = (const float4*)X;
        #pragma unroll 4
        for (int s = tid; s < 2048; s += 256) {
            int row = s >> 5, q = s & 31;
            float4 v = Xf4[(size_t)(m0 + row) * 32 + q];
            __half h0, h1, h2, h3, l0, l1, l2, l3;
            split_fp16(v.x, h0, l0); split_fp16(v.y, h1, l1);
            split_fp16(v.z, h2, l2); split_fp16(v.w, h3, l3);
            __half2 hA = __halves2half2(h0, h1), hB = __halves2half2(h2, h3);
            __half2 lA = __halves2half2(l0, l1), lB = __halves2half2(l2, l3);
            int off = row * 272 + q * 8;
            *(uint2*)(smem + G4_AH + off) = make_uint2(*(uint32_t*)&hA, *(uint32_t*)&hB);
            *(uint2*)(smem + G4_AL + off) = make_uint2(*(uint32_t*)&lA, *(uint32_t*)&lB);
        }
        __syncthreads();

        float C[2][4][4];
        #pragma unroll
        for (int mf = 0; mf < 2; mf++)
            #pragma unroll
            for (int nf = 0; nf < 4; nf++)
                #pragma unroll
                for (int q = 0; q < 4; q++) C[mf][nf][q] = 0.f;

        #pragma unroll
        for (int p = 0; p < 2; p++) {
            const uint32_t ab = abase[p] + aoff;
            #pragma unroll
            for (int ks = 0; ks < 8; ks++) {
                uint32_t a[2][4], b[2][4];
                ldsm4(a[0][0], a[0][1], a[0][2], a[0][3], ab + ks * 32);
                ldsm4(a[1][0], a[1][1], a[1][2], a[1][3], ab + 16 * 272 + ks * 32);
                ldsm4(b[0][0], b[0][1], b[0][2], b[0][3], bb + ks * 32);
                ldsm4(b[1][0], b[1][1], b[1][2], b[1][3], bb + 16 * 272 + ks * 32);
                #pragma unroll
                for (int mf = 0; mf < 2; mf++) {
                    mma16816h(C[mf][0], a[mf], b[0][0], b[0][1]);
                    mma16816h(C[mf][1], a[mf], b[0][2], b[0][3]);
                    mma16816h(C[mf][2], a[mf], b[1][0], b[1][1]);
                    mma16816h(C[mf][3], a[mf], b[1][2], b[1][3]);
                }
            }
        }

        #pragma unroll
        for (int mf = 0; mf < 2; mf++) {
            int row = m0 + wm * 32 + mf * 16 + qrow;
            #pragma unroll
            for (int nf = 0; nf < 4; nf++) {
                int colL = wn * 32 + nf * 8 + qcol;
                float b0 = bcs[colL], b1 = bcs[colL + 1];
                float* d0 = g_GI + (size_t)row * GATES + n0 + colL;
                *(float2*)d0 = make_float2(C[mf][nf][0] + b0, C[mf][nf][1] + b1);
                float* d1 = g_GI + (size_t)(row + 8) * GATES + n0 + colL;
                *(float2*)d1 = make_float2(C[mf][nf][2] + b0, C[mf][nf][3] + b1);
            }
        }
    }
}

// ---------------- HMMA GRU scan v8: R11 + end-of-step GI prefetch ----------------
#define VW_LO   0
#define VW_HI   104448
#define VH      0
#define VBH     4096
#define VSMEM   (104448 * 2)

__global__ __launch_bounds__(256, 1)
void gru_scan_hmma(const float* __restrict__ W_hh, const float* __restrict__ b_hh,
                   float* __restrict__ out) {
    extern __shared__ char smem[];
    const uint32_t sbase = smem_u32(smem);
    const int tid = threadIdx.x, w = tid >> 5, lane = tid & 31;
    const int r0 = blockIdx.x * 4;

    #pragma unroll 4
    for (int s = tid; s < 12288; s += 256) {
        int row = s >> 5, q = s & 31;
        float4 v = ((const float4*)W_hh)[s];
        __nv_bfloat16 h0, h1, h2, h3, l0, l1, l2, l3;
        split_bf16(v.x, h0, l0); split_bf16(v.y, h1, l1);
        split_bf16(v.z, h2, l2); split_bf16(v.w, h3, l3);
        __nv_bfloat162 hA(h0, h1), hB(h2, h3), lA(l0, l1), lB(l2, l3);
        int off = row * 272 + q * 8;
        *(uint2*)(smem + VW_HI + off) = make_uint2(*(uint32_t*)&hA, *(uint32_t*)&hB);
        *(uint2*)(smem + VW_LO + off) = make_uint2(*(uint32_t*)&lA, *(uint32_t*)&lB);
    }
    __syncthreads();

    uint32_t wh[3][8][4], wl[3][8][4];
    {
        const uint32_t lo_off = (uint32_t)(16 * w + (lane & 15)) * 272 + ((lane >> 4) << 4);
        #pragma unroll
        for (int g = 0; g < 3; g++)
            #pragma unroll
            for (int ks = 0; ks < 8; ks++) {
                ldsm4(wh[g][ks][0], wh[g][ks][1], wh[g][ks][2], wh[g][ks][3],
                      sbase + VW_HI + lo_off + (uint32_t)g * (128 * 272) + ks * 32);
                ldsm4(wl[g][ks][0], wl[g][ks][1], wl[g][ks][2], wl[g][ks][3],
                      sbase + VW_LO + lo_off + (uint32_t)g * (128 * 272) + ks * 32);
            }
    }
    __syncthreads();

    for (int s = tid; s < 512; s += 256)
        ((uint32_t*)(smem + VH))[s] = 0;
    for (int s = tid; s < GATES; s += 256)
        *(float*)(smem + VBH + s * 4) = b_hh[s];
    __syncthreads();

    const int jq = lane >> 2;
    const int j0 = 16 * w + jq, j1 = j0 + 8;
    const int bsel = lane & 3;
    const bool valid = (bsel < 2);
    const int b0 = 2 * bsel;

    const uint32_t bfb = sbase + VH + (uint32_t)(lane & 15) * 16;
    const float* bhs = (const float*)(smem + VBH);

    float hprev[4] = {0.f, 0.f, 0.f, 0.f};

    // preload GI for t=0
    float giv[3][4];
    #pragma unroll
    for (int q = 0; q < 4; q++) {
        if (valid) {
            int j = (q & 2) ? j1 : j0;
            int b = b0 + (q & 1);
            size_t base = (size_t)(r0 + b) * GATES + j;
            giv[0][q] = g_GI[base];
            giv[1][q] = g_GI[base + DIM];
            giv[2][q] = g_GI[base + 2 * DIM];
        } else {
            giv[0][q] = giv[1][q] = giv[2][q] = 0.f;
        }
    }

    for (int t = 0; t < T_STEPS; t++) {
        const int cur = t & 1;

        float Ch[3][4], Cl[3][4];
        #pragma unroll
        for (int g = 0; g < 3; g++)
            #pragma unroll
            for (int q = 0; q < 4; q++) { Ch[g][q] = 0.f; Cl[g][q] = 0.f; }

        const uint32_t hb = bfb + (uint32_t)cur * 2048;
        uint32_t bf0, bf1;
        ldsm2t(bf0, bf1, hb);
        #pragma unroll
        for (int ks = 0; ks < 8; ks++) {
            uint32_t nf0 = 0, nf1 = 0;
            if (ks < 7) ldsm2t(nf0, nf1, hb + (ks + 1) * 256);
            mma16816(Ch[0], wh[0][ks], bf0, bf1);
            mma16816(Ch[1], wh[1][ks], bf0, bf1);
            mma16816(Ch[2], wh[2][ks], bf0, bf1);
            mma16816(Cl[0], wl[0][ks], bf0, bf1);
            mma16816(Cl[1], wl[1][ks], bf0, bf1);
            mma16816(Cl[2], wl[2][ks], bf0, bf1);
            bf0 = nf0; bf1 = nf1;
        }

        float hnew[4];
        #pragma unroll
        for (int q = 0; q < 4; q++) {
            float gr = Ch[0][q] + Cl[0][q]; gr += __shfl_xor_sync(0xffffffffu, gr, 2);
            float gz = Ch[1][q] + Cl[1][q]; gz += __shfl_xor_sync(0xffffffffu, gz, 2);
            float gn = Ch[2][q] + Cl[2][q]; gn += __shfl_xor_sync(0xffffffffu, gn, 2);
            int j = (q & 2) ? j1 : j0;
            float r = sigm_fast(gr + bhs[j] + giv[0][q]);
            float z = sigm_fast(gz + bhs[DIM + j] + giv[1][q]);
            float n = tanhf_fast(giv[2][q] + r * (gn + bhs[2 * DIM + j]));
            hnew[q] = n + z * (hprev[q] - n);
            hprev[q] = hnew[q];
        }
        if (valid) {
            const uint32_t nb = VH + (uint32_t)(cur ^ 1) * 2048;
            #pragma unroll
            for (int q = 0; q < 4; q++) {
                int j = (q & 2) ? j1 : j0;
                int b = b0 + (q & 1);
                __nv_bfloat16 hh, hl;
                split_bf16(hnew[q], hh, hl);
                *(__nv_bfloat16*)(smem + nb + j * 16 + b * 2) = hh;
                *(__nv_bfloat16*)(smem + nb + j * 16 + 8 + b * 2) = hl;
            }
        }

        // prefetch GI for next step AFTER gates consumed giv; window spans
        // the barrier + next step's ldsm + mma region (fully hides DRAM latency)
        {
            const int tn = (t + 1 < T_STEPS) ? t + 1 : t;
            #pragma unroll
            for (int q = 0; q < 4; q++) {
                if (valid) {
                    int j = (q & 2) ? j1 : j0;
                    int b = b0 + (q & 1);
                    size_t base = ((size_t)tn * BATCH + r0 + b) * GATES + j;
                    giv[0][q] = g_GI[base];
                    giv[1][q] = g_GI[base + DIM];
                    giv[2][q] = g_GI[base + 2 * DIM];
                }
            }
        }
        __syncthreads();
    }

    if (valid) {
        #pragma unroll
        for (int q = 0; q < 4; q++) {
            int j = (q & 2) ? j1 : j0;
            int b = b0 + (q & 1);
            out[(r0 + b) * DIM + j] = hprev[q];
        }
    }
}

// ---------------- launch ----------------
extern "C" void kernel_launch(void* const* d_in, const int* in_sizes, int n_in,
                              void* d_out, int out_size) {
    const float* x    = (const float*)d_in[0];
    const float* W1   = (const float*)d_in[1];
    const float* b1   = (const float*)d_in[2];
    const float* W_ih = (const float*)d_in[3];
    const float* W_hh = (const float*)d_in[4];
    const float* b_ih = (const float*)d_in[5];
    const float* b_hh = (const float*)d_in[6];
    float* out = (float*)d_out;

    static bool attr_done = false;
    if (!attr_done) {
        cudaFuncSetAttribute(gi_gemm_hmma,
                             cudaFuncAttributeMaxDynamicSharedMemorySize, G4SMEM);
        cudaFuncSetAttribute(gru_scan_hmma,
                             cudaFuncAttributeMaxDynamicSharedMemorySize, VSMEM);
        attr_done = true;
    }

    prep_kernel<<<GATES, DIM>>>(W1, b1, W_ih, b_ih);
    gi_gemm_hmma<<<dim3(3, 1024), 256, G4SMEM>>>(x);
    gru_scan_hmma<<<128, 256, VSMEM>>>(W_hh, b_hh, out);
}

// round 16
// speedup vs baseline: 2.0757x; 1.1571x over previous
#include <cuda_runtime.h>
#include <cuda_bf16.h>
#include <cuda_fp16.h>
#include <cstdint>

#define T_STEPS 1024
#define BATCH   512
#define DIM     128
#define GATES   384

// ---------------- device scratch ----------------
__device__ float g_bc[GATES];
__device__ __half g_Wc16[3 * 16384];                     // Wc fp16: [nt][row][k]
__device__ float g_GI[(size_t)T_STEPS * BATCH * GATES];  // 805 MB scratch

// ---------------- helpers ----------------
__device__ __forceinline__ float tanhf_fast(float x) {
    float y; asm("tanh.approx.f32 %0, %1;" : "=f"(y) : "f"(x)); return y;
}
__device__ __forceinline__ float sigm_fast(float x) {
    return fmaf(0.5f, tanhf_fast(0.5f * x), 0.5f);
}
__device__ __forceinline__ uint32_t smem_u32(const void* p) {
    uint32_t a;
    asm("{ .reg .u64 t; cvta.to.shared.u64 t, %1; cvt.u32.u64 %0, t; }" : "=r"(a) : "l"(p));
    return a;
}
__device__ __forceinline__ void ldsm4(uint32_t& r0, uint32_t& r1, uint32_t& r2, uint32_t& r3,
                                      uint32_t addr) {
    asm volatile("ldmatrix.sync.aligned.m8n8.x4.shared.b16 {%0,%1,%2,%3}, [%4];"
                 : "=r"(r0), "=r"(r1), "=r"(r2), "=r"(r3) : "r"(addr));
}
__device__ __forceinline__ void ldsm2t(uint32_t& r0, uint32_t& r1, uint32_t addr) {
    asm volatile("ldmatrix.sync.aligned.m8n8.x2.trans.shared.b16 {%0,%1}, [%2];"
                 : "=r"(r0), "=r"(r1) : "r"(addr));
}
// fp16 mma
__device__ __forceinline__ void mma16816h(float* c, const uint32_t* a, uint32_t b0, uint32_t b1) {
    asm volatile(
        "mma.sync.aligned.m16n8k16.row.col.f32.f16.f16.f32 "
        "{%0,%1,%2,%3}, {%4,%5,%6,%7}, {%8,%9}, {%0,%1,%2,%3};"
        : "+f"(c[0]), "+f"(c[1]), "+f"(c[2]), "+f"(c[3])
        : "r"(a[0]), "r"(a[1]), "r"(a[2]), "r"(a[3]), "r"(b0), "r"(b1));
}
__device__ __forceinline__ void split_fp16(float v, __half& h, __half& l) {
    h = __float2half_rn(v);
    l = __float2half_rn(v - __half2float(h));
}

// ---------------- prep: fold fc1 into Wc (fp16) + bc ----------------
__global__ void prep_kernel(const float* __restrict__ W1, const float* __restrict__ b1,
                            const float* __restrict__ W_ih, const float* __restrict__ b_ih) {
    int bid = blockIdx.x, tid = threadIdx.x;
    __shared__ float wih[DIM];
    __shared__ float red[DIM];
    wih[tid] = W_ih[bid * DIM + tid];
    __syncthreads();
    float acc = 0.f;
    #pragma unroll 8
    for (int k = 0; k < DIM; k++)
        acc = fmaf(wih[k], W1[k * DIM + tid], acc);
    g_Wc16[bid * DIM + tid] = __float2half_rn(acc);
    red[tid] = wih[tid] * b1[tid];
    __syncthreads();
    if (tid == 0) {
        float s = 0.f;
        for (int k = 0; k < DIM; k++) s += red[k];
        g_bc[bid] = s + b_ih[bid];
    }
}

// ---------------- HMMA GI GEMM v5: single fp16 pass, resident B ----------------
// grid (3, 1024). Block: B (fp16) + bc staged once; 8 m-tiles of 64 rows. occ 2.
#define G5_BC   0
#define G5_B    1024
#define G5_A    (G5_B + 34816)
#define G5SMEM  (G5_A + 17408)           // 53248 B
#define MT5     8

__global__ __launch_bounds__(256, 2)
void gi_gemm_hmma(const float* __restrict__ X) {
    extern __shared__ char smem[];
    const uint32_t sbase = smem_u32(smem);
    const int tid = threadIdx.x;
    const int wid = tid >> 5, lane = tid & 31;
    const int nt = blockIdx.x;
    const int n0 = nt * 128;
    const int mbase = blockIdx.y * (MT5 * 64);

    // stage B (fp16) + bc once per block
    const uint4* B4 = (const uint4*)(g_Wc16 + nt * 16384);
    #pragma unroll 4
    for (int s = tid; s < 2048; s += 256) {
        int row = s >> 4, u = s & 15;
        *(uint4*)(smem + G5_B + row * 272 + u * 16) = B4[s];
    }
    if (tid < 128) *(float*)(smem + G5_BC + tid * 4) = g_bc[n0 + tid];
    __syncthreads();

    const int wm = wid & 1;
    const int wn = wid >> 1;
    const uint32_t aoff = (uint32_t)(wm * 32 + (lane & 15)) * 272 + ((lane >> 4) << 4);
    const uint32_t boff = (uint32_t)(wn * 32 + (lane & 7) + ((lane >> 4) << 3)) * 272
                        + (((lane >> 3) & 1) << 4);
    const float* bcs = (const float*)(smem + G5_BC);
    const int qrow = lane >> 2, qcol = (lane & 3) * 2;

    const uint32_t ab = sbase + G5_A + aoff;
    const uint32_t bb = sbase + G5_B + boff;

    for (int i = 0; i < MT5; i++) {
        const int m0 = mbase + i * 64;
        if (i > 0) __syncthreads();      // previous tile's A ldsm reads complete

        // stage A tile (fp32 -> fp16)
        const float4* Xf4 = (const float4*)X;
        #pragma unroll 4
        for (int s = tid; s < 2048; s += 256) {
            int row = s >> 5, q = s & 31;
            float4 v = Xf4[(size_t)(m0 + row) * 32 + q];
            __half2 hA = __halves2half2(__float2half_rn(v.x), __float2half_rn(v.y));
            __half2 hB = __halves2half2(__float2half_rn(v.z), __float2half_rn(v.w));
            *(uint2*)(smem + G5_A + row * 272 + q * 8)
                = make_uint2(*(uint32_t*)&hA, *(uint32_t*)&hB);
        }
        __syncthreads();

        float C[2][4][4];
        #pragma unroll
        for (int mf = 0; mf < 2; mf++)
            #pragma unroll
            for (int nf = 0; nf < 4; nf++)
                #pragma unroll
                for (int q = 0; q < 4; q++) C[mf][nf][q] = 0.f;

        #pragma unroll
        for (int ks = 0; ks < 8; ks++) {
            uint32_t a[2][4], b[2][4];
            ldsm4(a[0][0], a[0][1], a[0][2], a[0][3], ab + ks * 32);
            ldsm4(a[1][0], a[1][1], a[1][2], a[1][3], ab + 16 * 272 + ks * 32);
            ldsm4(b[0][0], b[0][1], b[0][2], b[0][3], bb + ks * 32);
            ldsm4(b[1][0], b[1][1], b[1][2], b[1][3], bb + 16 * 272 + ks * 32);
            #pragma unroll
            for (int mf = 0; mf < 2; mf++) {
                mma16816h(C[mf][0], a[mf], b[0][0], b[0][1]);
                mma16816h(C[mf][1], a[mf], b[0][2], b[0][3]);
                mma16816h(C[mf][2], a[mf], b[1][0], b[1][1]);
                mma16816h(C[mf][3], a[mf], b[1][2], b[1][3]);
            }
        }

        #pragma unroll
        for (int mf = 0; mf < 2; mf++) {
            int row = m0 + wm * 32 + mf * 16 + qrow;
            #pragma unroll
            for (int nf = 0; nf < 4; nf++) {
                int colL = wn * 32 + nf * 8 + qcol;
                float b0 = bcs[colL], b1 = bcs[colL + 1];
                float* d0 = g_GI + (size_t)row * GATES + n0 + colL;
                *(float2*)d0 = make_float2(C[mf][nf][0] + b0, C[mf][nf][1] + b1);
                float* d1 = g_GI + (size_t)(row + 8) * GATES + n0 + colL;
                *(float2*)d1 = make_float2(C[mf][nf][2] + b0, C[mf][nf][3] + b1);
            }
        }
    }
}

// ---------------- HMMA GRU scan v9: single fp16 W, h hi/lo in n-cols ----------
// 256 threads, 8 warps; warp w owns j in [16w,16w+16) for all 3 gates, full k.
// W_hh single fp16 fragments in regs (96 regs). h split fp16 hi(cols 0-3)/
// lo(cols 4-7); shfl-fold combines. 24 mma/warp/step, 3 chains depth 8.
#define VW      0                        // staging 384*272 = 104448
#define VH      0                        // h ping-pong (reuses staging): 2 x 2048
#define VBH     4096                     // b_hh copy
#define VSMEM   104448

__global__ __launch_bounds__(256, 1)
void gru_scan_hmma(const float* __restrict__ W_hh, const float* __restrict__ b_hh,
                   float* __restrict__ out) {
    extern __shared__ char smem[];
    const uint32_t sbase = smem_u32(smem);
    const int tid = threadIdx.x, w = tid >> 5, lane = tid & 31;
    const int r0 = blockIdx.x * 4;

    // stage W_hh -> fp16, 272B-padded rows
    #pragma unroll 4
    for (int s = tid; s < 12288; s += 256) {
        int row = s >> 5, q = s & 31;
        float4 v = ((const float4*)W_hh)[s];
        __half2 hA = __halves2half2(__float2half_rn(v.x), __float2half_rn(v.y));
        __half2 hB = __halves2half2(__float2half_rn(v.z), __float2half_rn(v.w));
        *(uint2*)(smem + VW + row * 272 + q * 8)
            = make_uint2(*(uint32_t*)&hA, *(uint32_t*)&hB);
    }
    __syncthreads();

    // preload W fragments: 3 gates x 8 ks = 96 regs
    uint32_t wf[3][8][4];
    {
        const uint32_t wo = sbase + VW
            + (uint32_t)(16 * w + (lane & 15)) * 272 + ((lane >> 4) << 4);
        #pragma unroll
        for (int g = 0; g < 3; g++)
            #pragma unroll
            for (int ks = 0; ks < 8; ks++)
                ldsm4(wf[g][ks][0], wf[g][ks][1], wf[g][ks][2], wf[g][ks][3],
                      wo + (uint32_t)g * (128 * 272) + ks * 32);
    }
    __syncthreads();   // staging reads done -> reuse region for h ping-pong + b_hh

    for (int s = tid; s < 512; s += 256)
        ((uint32_t*)(smem + VH))[s] = 0;
    for (int s = tid; s < GATES; s += 256)
        *(float*)(smem + VBH + s * 4) = b_hh[s];
    __syncthreads();

    const int jq = lane >> 2;
    const int j0 = 16 * w + jq, j1 = j0 + 8;
    const int bsel = lane & 3;
    const bool valid = (bsel < 2);
    const int b0 = 2 * bsel;

    const uint32_t bfb = sbase + VH + (uint32_t)(lane & 15) * 16;
    const float* bhs = (const float*)(smem + VBH);

    float hprev[4] = {0.f, 0.f, 0.f, 0.f};

    // preload GI for t=0
    float giv[3][4];
    #pragma unroll
    for (int q = 0; q < 4; q++) {
        if (valid) {
            int j = (q & 2) ? j1 : j0;
            int b = b0 + (q & 1);
            size_t base = (size_t)(r0 + b) * GATES + j;
            giv[0][q] = g_GI[base];
            giv[1][q] = g_GI[base + DIM];
            giv[2][q] = g_GI[base + 2 * DIM];
        } else {
            giv[0][q] = giv[1][q] = giv[2][q] = 0.f;
        }
    }

    for (int t = 0; t < T_STEPS; t++) {
        const int cur = t & 1;

        float C[3][4];
        #pragma unroll
        for (int g = 0; g < 3; g++)
            #pragma unroll
            for (int q = 0; q < 4; q++) C[g][q] = 0.f;

        const uint32_t hb = bfb + (uint32_t)cur * 2048;
        uint32_t bf0, bf1;
        ldsm2t(bf0, bf1, hb);
        #pragma unroll
        for (int ks = 0; ks < 8; ks++) {
            uint32_t nf0 = 0, nf1 = 0;
            if (ks < 7) ldsm2t(nf0, nf1, hb + (ks + 1) * 256);
            mma16816h(C[0], wf[0][ks], bf0, bf1);
            mma16816h(C[1], wf[1][ks], bf0, bf1);
            mma16816h(C[2], wf[2][ks], bf0, bf1);
            bf0 = nf0; bf1 = nf1;
        }

        float hnew[4];
        #pragma unroll
        for (int q = 0; q < 4; q++) {
            float gr = C[0][q]; gr += __shfl_xor_sync(0xffffffffu, gr, 2);
            float gz = C[1][q]; gz += __shfl_xor_sync(0xffffffffu, gz, 2);
            float gn = C[2][q]; gn += __shfl_xor_sync(0xffffffffu, gn, 2);
            int j = (q & 2) ? j1 : j0;
            float r = sigm_fast(gr + bhs[j] + giv[0][q]);
            float z = sigm_fast(gz + bhs[DIM + j] + giv[1][q]);
            float n = tanhf_fast(giv[2][q] + r * (gn + bhs[2 * DIM + j]));
            hnew[q] = n + z * (hprev[q] - n);
            hprev[q] = hnew[q];
        }
        if (valid) {
            const uint32_t nb = VH + (uint32_t)(cur ^ 1) * 2048;
            #pragma unroll
            for (int q = 0; q < 4; q++) {
                int j = (q & 2) ? j1 : j0;
                int b = b0 + (q & 1);
                __half hh, hl;
                split_fp16(hnew[q], hh, hl);
                *(__half*)(smem + nb + j * 16 + b * 2) = hh;
                *(__half*)(smem + nb + j * 16 + 8 + b * 2) = hl;
            }
        }

        // prefetch GI for next step (after giv consumed; window spans barrier+mma)
        {
            const int tn = (t + 1 < T_STEPS) ? t + 1 : t;
            #pragma unroll
            for (int q = 0; q < 4; q++) {
                if (valid) {
                    int j = (q & 2) ? j1 : j0;
                    int b = b0 + (q & 1);
                    size_t base = ((size_t)tn * BATCH + r0 + b) * GATES + j;
                    giv[0][q] = g_GI[base];
                    giv[1][q] = g_GI[base + DIM];
                    giv[2][q] = g_GI[base + 2 * DIM];
                }
            }
        }
        __syncthreads();
    }

    if (valid) {
        #pragma unroll
        for (int q = 0; q < 4; q++) {
            int j = (q & 2) ? j1 : j0;
            int b = b0 + (q & 1);
            out[(r0 + b) * DIM + j] = hprev[q];
        }
    }
}

// ---------------- launch ----------------
extern "C" void kernel_launch(void* const* d_in, const int* in_sizes, int n_in,
                              void* d_out, int out_size) {
    const float* x    = (const float*)d_in[0];
    const float* W1   = (const float*)d_in[1];
    const float* b1   = (const float*)d_in[2];
    const float* W_ih = (const float*)d_in[3];
    const float* W_hh = (const float*)d_in[4];
    const float* b_ih = (const float*)d_in[5];
    const float* b_hh = (const float*)d_in[6];
    float* out = (float*)d_out;

    static bool attr_done = false;
    if (!attr_done) {
        cudaFuncSetAttribute(gi_gemm_hmma,
                             cudaFuncAttributeMaxDynamicSharedMemorySize, G5SMEM);
        cudaFuncSetAttribute(gru_scan_hmma,
                             cudaFuncAttributeMaxDynamicSharedMemorySize, VSMEM);
        attr_done = true;
    }

    prep_kernel<<<GATES, DIM>>>(W1, b1, W_ih, b_ih);
    gi_gemm_hmma<<<dim3(3, 1024), 256, G5SMEM>>>(x);
    gru_scan_hmma<<<128, 256, VSMEM>>>(W_hh, b_hh, out);
}